// round 16
// baseline (speedup 1.0000x reference)
#include <cuda_runtime.h>
#include <math.h>
#include <float.h>
#include <stdint.h>

#define NN   100000
#define DD   128
#define HH   8
#define CC   16
#define EE   800000
#define ETOT (EE + NN)
#define NEG  0.2f
#define NTILES ((NN + 127) / 128)

// ---------------- scratch (static __device__ — no allocations) ----------------
__device__ float g_h[NN * DD];            // 51.2 MB projected features
__device__ float g_asrc[NN * HH];
__device__ float g_adst[NN * HH];
__device__ float g_ex[(size_t)ETOT * HH];
__device__ int   g_src[ETOT];
__device__ int   g_dst[ETOT];
__device__ int   g_pos[ETOT];
__device__ int   g_csr[ETOT];
__device__ int   g_count[NN + 1];         // [NN] = global scan cursor
__device__ int   g_rowstart[NN];
__device__ float g_invd[NN * HH];

// ---------------- f32x2 packed-FMA helpers ----------------
typedef unsigned long long ull;
__device__ __forceinline__ ull pk(float a, float b) {
    ull r; asm("mov.b64 %0, {%1,%2};" : "=l"(r) : "f"(a), "f"(b)); return r;
}
__device__ __forceinline__ void upk(ull v, float& a, float& b) {
    asm("mov.b64 {%0,%1}, %2;" : "=f"(a), "=f"(b) : "l"(v));
}
__device__ __forceinline__ ull f2fma(ull a, ull b, ull c) {
    ull d; asm("fma.rn.f32x2 %0, %1, %2, %3;" : "=l"(d) : "l"(a), "l"(b), "l"(c)); return d;
}

__device__ __forceinline__ float leaky(float v) { return v > 0.0f ? v : NEG * v; }
__device__ __forceinline__ int clampN(int v) {
    v = v < 0 ? 0 : v;
    return v >= NN ? NN - 1 : v;
}

// ---------------- GEMM h = x @ W : 8x8 register tile, f32x2 ----------------
// 256 threads / 8 warps; tile = 128 rows x 128 cols per CTA.
// Warp w: rows (w>>1)*32 .. +31, cols (w&1)*64 .. +63.
// Lane (ty=lane>>3, tx=lane&7): cols cw+tx*8..+7; rows rw + i*8 + ty*2 + j (i=0..3, j=0..1).
// smem: sW[k][c] 64KB; sX: duplicated (x,x) pairs, sX[k][row] 8B each = 131KB.
__global__ void __launch_bounds__(256, 1)
gemm_kernel(const float* __restrict__ x, const float* __restrict__ W,
            const float* __restrict__ attS, const float* __restrict__ attD) {
    extern __shared__ char smem[];
    float* sW = (float*)smem;                 // [128][128] floats
    ull*   sX = (ull*)(smem + 65536);         // [128][128] pairs
    int tid  = threadIdx.x;
    int wid  = tid >> 5;
    int lane = tid & 31;
    int row0 = blockIdx.x * 128;

    // load W (16384 floats = 4096 float4)
    for (int i = tid; i < 4096; i += 256)
        ((float4*)sW)[i] = ((const float4*)W)[i];

    // stage x transposed + duplicated: thread owns (row = tid&127, kc = tid>>7)
    {
        int row = tid & 127, kc = tid >> 7;
        int rc  = row0 + row; if (rc >= NN) rc = NN - 1;
        const float4* xr = (const float4*)(x + (size_t)rc * 128);
        #pragma unroll
        for (int i = 0; i < 16; ++i) {
            int k = kc * 64 + i * 4;
            float4 v = xr[k >> 2];
            sX[(size_t)(k + 0) * 128 + row] = pk(v.x, v.x);
            sX[(size_t)(k + 1) * 128 + row] = pk(v.y, v.y);
            sX[(size_t)(k + 2) * 128 + row] = pk(v.z, v.z);
            sX[(size_t)(k + 3) * 128 + row] = pk(v.w, v.w);
        }
    }
    __syncthreads();

    int ty = lane >> 3, tx = lane & 7;
    int rw = (wid >> 1) * 32;
    int cw = (wid & 1) * 64;
    int colbase = cw + tx * 8;

    ull acc[8][4];
    #pragma unroll
    for (int r = 0; r < 8; ++r)
        #pragma unroll
        for (int c = 0; c < 4; ++c) acc[r][c] = 0ull;

    #pragma unroll 4
    for (int k = 0; k < 128; ++k) {
        const ull* wrow = (const ull*)(sW + k * 128 + colbase);
        ull w0 = wrow[0], w1 = wrow[1], w2 = wrow[2], w3 = wrow[3];
        const ull* xrow = sX + (size_t)k * 128 + rw + ty * 2;
        #pragma unroll
        for (int i = 0; i < 4; ++i) {
            ulonglong2 xp = ((const ulonglong2*)(xrow + i * 8))[0];  // rows i*8+ty*2, +1
            acc[i*2][0]   = f2fma(xp.x, w0, acc[i*2][0]);
            acc[i*2][1]   = f2fma(xp.x, w1, acc[i*2][1]);
            acc[i*2][2]   = f2fma(xp.x, w2, acc[i*2][2]);
            acc[i*2][3]   = f2fma(xp.x, w3, acc[i*2][3]);
            acc[i*2+1][0] = f2fma(xp.y, w0, acc[i*2+1][0]);
            acc[i*2+1][1] = f2fma(xp.y, w1, acc[i*2+1][1]);
            acc[i*2+1][2] = f2fma(xp.y, w2, acc[i*2+1][2]);
            acc[i*2+1][3] = f2fma(xp.y, w3, acc[i*2+1][3]);
        }
    }

    // epilogue: att vectors are flat over 128 cols (att[h][c] == att_flat[h*16+c])
    float4 as0 = ((const float4*)(attS + colbase))[0];
    float4 as1 = ((const float4*)(attS + colbase))[1];
    float4 ad0 = ((const float4*)(attD + colbase))[0];
    float4 ad1 = ((const float4*)(attD + colbase))[1];
    int head = (colbase >> 4);   // = cw/16 + (tx>>1)

    #pragma unroll
    for (int r = 0; r < 8; ++r) {
        int i = r >> 1, j = r & 1;
        int row = row0 + rw + i * 8 + ty * 2 + j;
        float c0, c1, c2, c3, c4, c5, c6, c7;
        upk(acc[r][0], c0, c1); upk(acc[r][1], c2, c3);
        upk(acc[r][2], c4, c5); upk(acc[r][3], c6, c7);

        float s = c0*as0.x + c1*as0.y + c2*as0.z + c3*as0.w
                + c4*as1.x + c5*as1.y + c6*as1.z + c7*as1.w;
        float d = c0*ad0.x + c1*ad0.y + c2*ad0.z + c3*ad0.w
                + c4*ad1.x + c5*ad1.y + c6*ad1.z + c7*ad1.w;
        s += __shfl_xor_sync(0xFFFFFFFFu, s, 1);   // combine tx pair (same rows)
        d += __shfl_xor_sync(0xFFFFFFFFu, d, 1);

        if (row < NN) {
            float4* hp = (float4*)(g_h + (size_t)row * 128 + colbase);
            hp[0] = make_float4(c0, c1, c2, c3);
            hp[1] = make_float4(c4, c5, c6, c7);
            if ((tx & 1) == 0) {
                g_asrc[row * 8 + head] = s;
                g_adst[row * 8 + head] = d;
            }
        }
    }
}

// ---------------- count pass (src/dst/pos + degree) ----------------
__global__ void count_kernel(const int* __restrict__ ei) {
    int e = blockIdx.x * blockDim.x + threadIdx.x;
    if (e >= ETOT) return;
    int s, d;
    if (e < EE) { s = clampN(ei[e]); d = clampN(ei[EE + e]); }
    else        { s = e - EE; d = s; }
    g_src[e] = s;
    g_dst[e] = d;
    g_pos[e] = atomicAdd(&g_count[d], 1);
}

// ---------------- single-kernel scan (atomic block offset) ----------------
__global__ void scan_kernel() {
    __shared__ int sm[1024];
    __shared__ int sbase;
    int t   = threadIdx.x;
    int idx = blockIdx.x * 1024 + t;
    int v = (idx < NN) ? g_count[idx] : 0;
    sm[t] = v;
    __syncthreads();
    for (int off = 1; off < 1024; off <<= 1) {
        int add = (t >= off) ? sm[t - off] : 0;
        __syncthreads();
        sm[t] += add;
        __syncthreads();
    }
    if (t == 1023)
        sbase = atomicAdd(&g_count[NN], sm[1023]);
    __syncthreads();
    if (idx < NN)
        g_rowstart[idx] = sbase + sm[t] - v;
}

// ---------------- ei output ----------------
__global__ void eiout_kernel(float* __restrict__ eo) {
    int e = blockIdx.x * blockDim.x + threadIdx.x;
    if (e >= ETOT) return;
    eo[e]        = (float)g_src[e];
    eo[ETOT + e] = (float)g_dst[e];
}

// ---------------- edge pass: exp(leaky) written at SORTED position ----------------
__global__ void edge_sorted_kernel() {
    int e = blockIdx.x * blockDim.x + threadIdx.x;
    if (e >= ETOT) return;
    int s = g_src[e], d = g_dst[e];
    int p = g_rowstart[d] + g_pos[e];

    float4 as0 = ((const float4*)&g_asrc[s * 8])[0];
    float4 as1 = ((const float4*)&g_asrc[s * 8])[1];
    float4 ad0 = ((const float4*)&g_adst[d * 8])[0];
    float4 ad1 = ((const float4*)&g_adst[d * 8])[1];

    float4* exp4 = (float4*)&g_ex[(size_t)p * 8];
    exp4[0] = make_float4(__expf(leaky(as0.x + ad0.x)), __expf(leaky(as0.y + ad0.y)),
                          __expf(leaky(as0.z + ad0.z)), __expf(leaky(as0.w + ad0.w)));
    exp4[1] = make_float4(__expf(leaky(as1.x + ad1.x)), __expf(leaky(as1.y + ad1.y)),
                          __expf(leaky(as1.z + ad1.z)), __expf(leaky(as1.w + ad1.w)));
    g_csr[p] = s;
}

// ---------------- warp-per-destination gather ----------------
__global__ void gather_kernel(float* __restrict__ out, const float* __restrict__ bias,
                              int storeInvd) {
    int gwarp = (blockIdx.x * blockDim.x + threadIdx.x) >> 5;
    int lane  = threadIdx.x & 31;
    if (gwarp >= NN) return;
    int d    = gwarp;
    int cnt  = g_count[d];
    int rs   = g_rowstart[d];
    int head = lane >> 2;

    float4 acc = make_float4(0.f, 0.f, 0.f, 0.f);
    float  sden = 0.0f;

    int j = 0;
    for (; j + 4 <= cnt; j += 4) {
        int p = rs + j;
        int s0 = g_csr[p], s1 = g_csr[p + 1], s2 = g_csr[p + 2], s3 = g_csr[p + 3];
        float a0 = g_ex[(size_t)p * 8 + head];
        float a1 = g_ex[(size_t)(p + 1) * 8 + head];
        float a2 = g_ex[(size_t)(p + 2) * 8 + head];
        float a3 = g_ex[(size_t)(p + 3) * 8 + head];
        float4 h0 = ((const float4*)g_h)[(size_t)s0 * 32 + lane];
        float4 h1 = ((const float4*)g_h)[(size_t)s1 * 32 + lane];
        float4 h2 = ((const float4*)g_h)[(size_t)s2 * 32 + lane];
        float4 h3 = ((const float4*)g_h)[(size_t)s3 * 32 + lane];
        sden += (a0 + a1) + (a2 + a3);
        acc.x = fmaf(a0, h0.x, acc.x); acc.y = fmaf(a0, h0.y, acc.y);
        acc.z = fmaf(a0, h0.z, acc.z); acc.w = fmaf(a0, h0.w, acc.w);
        acc.x = fmaf(a1, h1.x, acc.x); acc.y = fmaf(a1, h1.y, acc.y);
        acc.z = fmaf(a1, h1.z, acc.z); acc.w = fmaf(a1, h1.w, acc.w);
        acc.x = fmaf(a2, h2.x, acc.x); acc.y = fmaf(a2, h2.y, acc.y);
        acc.z = fmaf(a2, h2.z, acc.z); acc.w = fmaf(a2, h2.w, acc.w);
        acc.x = fmaf(a3, h3.x, acc.x); acc.y = fmaf(a3, h3.y, acc.y);
        acc.z = fmaf(a3, h3.z, acc.z); acc.w = fmaf(a3, h3.w, acc.w);
    }
    for (; j < cnt; ++j) {
        int p = rs + j;
        int s0 = g_csr[p];
        float a0 = g_ex[(size_t)p * 8 + head];
        float4 h0 = ((const float4*)g_h)[(size_t)s0 * 32 + lane];
        sden += a0;
        acc.x = fmaf(a0, h0.x, acc.x); acc.y = fmaf(a0, h0.y, acc.y);
        acc.z = fmaf(a0, h0.z, acc.z); acc.w = fmaf(a0, h0.w, acc.w);
    }

    float invd = 1.0f / (sden + 1e-16f);
    float4 b4 = ((const float4*)bias)[lane];
    acc.x = fmaf(acc.x, invd, b4.x);
    acc.y = fmaf(acc.y, invd, b4.y);
    acc.z = fmaf(acc.z, invd, b4.z);
    acc.w = fmaf(acc.w, invd, b4.w);
    ((float4*)out)[(size_t)d * 32 + lane] = acc;

    if (storeInvd && (lane & 3) == 0)
        g_invd[d * 8 + head] = invd;
}

// ---------------- alpha output ----------------
__global__ void alpha_kernel(float* __restrict__ alphaOut) {
    int e = blockIdx.x * blockDim.x + threadIdx.x;
    if (e >= ETOT) return;
    int d = g_dst[e];
    int p = g_rowstart[d] + g_pos[e];
    float4 e0 = ((const float4*)g_ex)[(size_t)p * 2];
    float4 e1 = ((const float4*)g_ex)[(size_t)p * 2 + 1];
    float4 v0 = ((const float4*)g_invd)[(size_t)d * 2];
    float4 v1 = ((const float4*)g_invd)[(size_t)d * 2 + 1];
    ((float4*)alphaOut)[(size_t)e * 2]     = make_float4(e0.x * v0.x, e0.y * v0.y, e0.z * v0.z, e0.w * v0.w);
    ((float4*)alphaOut)[(size_t)e * 2 + 1] = make_float4(e1.x * v1.x, e1.y * v1.y, e1.z * v1.z, e1.w * v1.w);
}

// ---------------- launch ----------------
extern "C" void kernel_launch(void* const* d_in, const int* in_sizes, int n_in,
                              void* d_out, int out_size) {
    const float* x    = (const float*)d_in[0];
    const int*   ei   = (const int*)d_in[1];
    const float* W    = (const float*)d_in[2];
    const float* attS = (const float*)d_in[3];
    const float* attD = (const float*)d_in[4];
    const float* bias = (const float*)d_in[5];
    float* out = (float*)d_out;

    const long long OUT_ELEMS  = (long long)NN * DD;
    const long long FULL_ELEMS = OUT_ELEMS + 2LL * ETOT + (long long)ETOT * HH;
    bool full = ((long long)out_size >= FULL_ELEMS);
    float* eiOut    = full ? out + OUT_ELEMS              : nullptr;
    float* alphaOut = full ? out + OUT_ELEMS + 2LL * ETOT : nullptr;

    const int gemmSmem = 65536 + 131072; // 192 KB
    cudaFuncSetAttribute(gemm_kernel, cudaFuncAttributeMaxDynamicSharedMemorySize, gemmSmem);

    void* countPtr = nullptr;
    cudaGetSymbolAddress(&countPtr, g_count);
    cudaMemsetAsync(countPtr, 0, (NN + 1) * sizeof(int));

    count_kernel<<<(ETOT + 255) / 256, 256>>>(ei);
    scan_kernel<<<(NN + 1023) / 1024, 1024>>>();
    if (full)
        eiout_kernel<<<(ETOT + 255) / 256, 256>>>(eiOut);
    gemm_kernel<<<NTILES, 256, gemmSmem>>>(x, W, attS, attD);
    edge_sorted_kernel<<<(ETOT + 255) / 256, 256>>>();
    gather_kernel<<<(NN * 32 + 255) / 256, 256>>>(out, bias, full ? 1 : 0);
    if (full)
        alpha_kernel<<<(ETOT + 255) / 256, 256>>>(alphaOut);
}